// round 8
// baseline (speedup 1.0000x reference)
#include <cuda_runtime.h>
#include <cstdint>

#define DIM 128
#define NSLICE 16          // CTAs per cluster = k-slices per batch
#define NTHREADS 256       // 8 warps per block
#define NBATCH 8

__device__ __forceinline__ uint32_t smem_u32(const void* p) {
    return (uint32_t)__cvta_generic_to_shared(p);
}

// store v into the smem of cluster CTA `rank` at the same offset as laddr
__device__ __forceinline__ void st_cluster_f32(uint32_t laddr, int rank, float v) {
    uint32_t raddr;
    asm volatile("mapa.shared::cluster.u32 %0, %1, %2;"
                 : "=r"(raddr) : "r"(laddr), "r"(rank));
    asm volatile("st.shared::cluster.f32 [%0], %1;"
                 :: "r"(raddr), "f"(v) : "memory");
}

// full cluster barrier (release on arrive covers prior shared::cluster stores,
// acquire on wait covers subsequent smem reads); subsumes __syncthreads
__device__ __forceinline__ void cluster_sync_() {
    asm volatile("barrier.cluster.arrive.aligned;" ::: "memory");
    asm volatile("barrier.cluster.wait.aligned;" ::: "memory");
}

__device__ __forceinline__ float prelu_f(float x, float a) {
    return x >= 0.0f ? x : a * x;
}

// xor-butterfly: full sum in EVERY lane
__device__ __forceinline__ float wred(float v) {
    v += __shfl_xor_sync(0xffffffffu, v, 16);
    v += __shfl_xor_sync(0xffffffffu, v, 8);
    v += __shfl_xor_sync(0xffffffffu, v, 4);
    v += __shfl_xor_sync(0xffffffffu, v, 2);
    v += __shfl_xor_sync(0xffffffffu, v, 1);
    return v;
}

__device__ __forceinline__ float dot4(float4 a, float4 b) {
    return fmaf(a.x, b.x, fmaf(a.y, b.y, fmaf(a.z, b.z, a.w * b.w)));
}

__global__ __launch_bounds__(NTHREADS, 1) __cluster_dims__(NSLICE, 1, 1)
void encoder_fused_kernel(
    const float* __restrict__ points,  // [B, N3, 3]
    const float* __restrict__ vec2,    // [B, N2, 3]
    const float* __restrict__ vec1,    // [B, N1, 3]
    const float* __restrict__ vec0,    // [B, 1, 3]
    const float* __restrict__ Wp,      // [DIM, 3]
    const float* __restrict__ bp,
    const float* __restrict__ a_leaf,
    const float* __restrict__ Wb2, const float* __restrict__ bb2,
    const float* __restrict__ a2p,
    const float* __restrict__ Wb1, const float* __restrict__ bb1,
    const float* __restrict__ Ws1, const float* __restrict__ bs1,
    const float* __restrict__ a1p,
    const float* __restrict__ Wb0, const float* __restrict__ bb0,
    const float* __restrict__ Ws0, const float* __restrict__ bs0,
    const float* __restrict__ a0p,
    const int* __restrict__ cl2, const int* __restrict__ cr2,
    const int* __restrict__ cl1, const int* __restrict__ cr1,
    const int* __restrict__ cs1,
    const int* __restrict__ cl0, const int* __restrict__ cr0,
    const int* __restrict__ cs0,
    float* __restrict__ out,           // [B, DIM]
    int N3, int N2n, int N1n)
{
    const int b   = blockIdx.x >> 4;            // batch = cluster id
    const int s   = blockIdx.x & (NSLICE - 1);  // cluster rank = k-slice
    const int tid = threadIdx.x;
    const int w   = tid >> 5, l = tid & 31;

    // ---------------- register-preload ALL weight slices (no dependencies) ----------------
    const int kB  = (s << 3) + w;           // phase B/E/F channel
    const int idx = (s << 4) + (w << 1);    // phase C/D pair base
    const int jCD = idx >> 7;
    const int k0  = idx & 127, k1 = k0 + 1;

    float4 wB[6], wC0[6], wC1[6], wE[6];
    float4 wD0[2], wD1[2], wF[2];
    {
        const float4* p1 = (const float4*)Wb2 + (long)kB * 192;
        const float4* p2 = (const float4*)Wb1 + (long)k0 * 192;
        const float4* p3 = (const float4*)Wb1 + (long)k1 * 192;
        const float4* p4 = (const float4*)Wb0 + (long)kB * 192;
        #pragma unroll
        for (int t = 0; t < 6; t++) {
            wB[t]  = p1[t * 32 + l];
            wC0[t] = p2[t * 32 + l];
            wC1[t] = p3[t * 32 + l];
            wE[t]  = p4[t * 32 + l];
        }
        const float4* p5 = (const float4*)Ws1 + (long)k0 * 64;
        const float4* p6 = (const float4*)Ws1 + (long)k1 * 64;
        const float4* p7 = (const float4*)Ws0 + (long)kB * 64;
        wD0[0] = p5[l]; wD0[1] = p5[32 + l];
        wD1[0] = p6[l]; wD1[1] = p6[32 + l];
        wF[0]  = p7[l]; wF[1]  = p7[32 + l];
    }
    const float bB  = bb2[kB];
    const float bC0 = bb1[k0], bC1 = bb1[k1];
    const float bD0 = bs1[k0], bD1 = bs1[k1];
    const float bE  = bb0[kB], bF = bs0[kB];
    const float AL = a_leaf[0], A2 = a2p[0], A1 = a1p[0], A0 = a0p[0];

    __shared__ int sp[12], sn2[5], sl1[2];
    __shared__ __align__(16) float svec2[5][3];
    __shared__ __align__(16) float svec1[2][3];
    __shared__ __align__(16) float svec0[3];
    __shared__ __align__(16) float leaf[12][DIM];
    __shared__ __align__(16) float zbuf[5 * 768];   // z2 -> z1 -> z0 (reused)
    // DSMEM exchange targets (peers write directly into these):
    __shared__ __align__(16) float h2all[5][DIM];
    __shared__ __align__(16) float tbs[2][DIM];
    __shared__ __align__(16) float h1all[2][DIM];
    __shared__ __align__(16) float tb0s[DIM];

    // ---- resolve the (batch-invariant) dependency cone ----
    if (tid == 0) {
        int l1a = cl0[0];
        int l1b = cr0[0];
        sl1[0] = l1a; sl1[1] = l1b;
        int n0 = cl1[l1a], n1 = cr1[l1a], n2_ = cl1[l1b], n3 = cr1[l1b], n4 = cs0[0];
        sn2[0] = n0; sn2[1] = n1; sn2[2] = n2_; sn2[3] = n3; sn2[4] = n4;
        sp[0] = cl2[n0];  sp[1] = cr2[n0];
        sp[2] = cl2[n1];  sp[3] = cr2[n1];
        sp[4] = cl2[n2_]; sp[5] = cr2[n2_];
        sp[6] = cl2[n3];  sp[7] = cr2[n3];
        sp[8] = cl2[n4];  sp[9] = cr2[n4];
        sp[10] = cs1[l1a]; sp[11] = cs1[l1b];
    }
    __syncthreads();

    // ---- preload vec gathers into smem ----
    if (tid < 15) {
        int j = tid / 3, v = tid - 3 * j;
        svec2[j][v] = vec2[((long)b * N2n + sn2[j]) * 3 + v];
    } else if (tid < 21) {
        int t = tid - 15;
        int j = t / 3, v = t - 3 * j;
        svec1[j][v] = vec1[((long)b * N1n + sl1[j]) * 3 + v];
    } else if (tid < 24) {
        svec0[tid - 21] = vec0[(long)b * 3 + (tid - 21)];
    }

    // ---- leaves: 12 rows, h3 = prelu(points @ Wp^T + bp) ----
    for (int i = tid; i < 12 * DIM; i += NTHREADS) {
        int j = i >> 7, k = i & 127;
        const float* pt = points + ((long)b * N3 + sp[j]) * 3;
        float h = fmaf(Wp[k * 3 + 0], pt[0],
                  fmaf(Wp[k * 3 + 1], pt[1],
                  fmaf(Wp[k * 3 + 2], pt[2], bp[k])));
        leaf[j][k] = prelu_f(h, AL);
    }
    __syncthreads();

    // ---- z2 build (smem-only) ----
    for (int i = tid; i < 5 * 768; i += NTHREADS) {
        int j = i / 768;
        int e = i - j * 768;
        unsigned d = (unsigned)e / 3u;
        int v = e - 3 * (int)d;
        zbuf[i] = leaf[2 * j + (d >> 7)][d & 127] * svec2[j][v];
    }
    __syncthreads();

    // ---- Phase B: layer-2 bilinear; scatter h2 to all 16 CTAs via DSMEM ----
    {
        const float4* zr = (const float4*)zbuf;
        float acc[5] = {0.f, 0.f, 0.f, 0.f, 0.f};
        #pragma unroll
        for (int t = 0; t < 6; t++) {
            #pragma unroll
            for (int j = 0; j < 5; j++)
                acc[j] += dot4(wB[t], zr[j * 192 + t * 32 + l]);
        }
        #pragma unroll
        for (int j = 0; j < 5; j++) {
            float r = wred(acc[j]);                    // valid in every lane
            float val = prelu_f(r + bB, A2);
            if (l < NSLICE)                            // lane i -> rank i
                st_cluster_f32(smem_u32(&h2all[j][kB]), l, val);
        }
    }
    cluster_sync_();

    // ---- z1 build (h2 already in local smem) ----
    for (int i = tid; i < 2 * 768; i += NTHREADS) {
        int j = i >= 768 ? 1 : 0;
        int e = i - j * 768;
        unsigned d = (unsigned)e / 3u;
        int v = e - 3 * (int)d;
        zbuf[i] = h2all[2 * j + (d >> 7)][d & 127] * svec1[j][v];
    }
    __syncthreads();

    // ---- Phase C: layer-1 bilinear; scatter tb ----
    {
        const float4* zr = (const float4*)(zbuf + jCD * 768);
        float a0 = 0.f, a1 = 0.f;
        #pragma unroll
        for (int t = 0; t < 6; t++) {
            float4 zz = zr[t * 32 + l];
            a0 += dot4(wC0[t], zz);
            a1 += dot4(wC1[t], zz);
        }
        float r0 = wred(a0), r1 = wred(a1);
        float v0 = prelu_f(r0 + bC0, A1);
        float v1 = prelu_f(r1 + bC1, A1);
        if (l < NSLICE)
            st_cluster_f32(smem_u32(&tbs[jCD][k0]), l, v0);
        else
            st_cluster_f32(smem_u32(&tbs[jCD][k1]), l - NSLICE, v1);
    }
    cluster_sync_();

    // ---- Phase D: sample-merge linear; scatter h1 ----
    {
        float4 xa = ((const float4*)tbs[jCD])[l];
        float4 xb = ((const float4*)leaf[10 + jCD])[l];
        float a0 = dot4(wD0[0], xa) + dot4(wD0[1], xb);
        float a1 = dot4(wD1[0], xa) + dot4(wD1[1], xb);
        float r0 = wred(a0), r1 = wred(a1);
        float v0 = prelu_f(r0 + bD0, A1);
        float v1 = prelu_f(r1 + bD1, A1);
        if (l < NSLICE)
            st_cluster_f32(smem_u32(&h1all[jCD][k0]), l, v0);
        else
            st_cluster_f32(smem_u32(&h1all[jCD][k1]), l - NSLICE, v1);
    }
    cluster_sync_();

    // ---- z0 build (h1 already in local smem) ----
    for (int e = tid; e < 768; e += NTHREADS) {
        unsigned d = (unsigned)e / 3u;
        int v = e - 3 * (int)d;
        zbuf[e] = h1all[d >> 7][d & 127] * svec0[v];
    }
    __syncthreads();

    // ---- Phase E: root bilinear; scatter tb0 ----
    {
        const float4* zr = (const float4*)zbuf;
        float acc = 0.f;
        #pragma unroll
        for (int t = 0; t < 6; t++)
            acc += dot4(wE[t], zr[t * 32 + l]);
        float r = wred(acc);
        float val = prelu_f(r + bE, A0);
        if (l < NSLICE)
            st_cluster_f32(smem_u32(&tb0s[kB]), l, val);
    }
    cluster_sync_();

    // ---- Phase F: root linear (tb0 already in local smem) ----
    {
        float acc = dot4(wF[0], ((const float4*)tb0s)[l]);
        acc      += dot4(wF[1], ((const float4*)h2all[4])[l]);
        float r = wred(acc);
        if (l == 0) out[(long)b * DIM + kB] = prelu_f(r + bF, A0);
    }
}

extern "C" void kernel_launch(void* const* d_in, const int* in_sizes, int n_in,
                              void* d_out, int out_size)
{
    const float* points = (const float*)d_in[0];
    const float* vec2   = (const float*)d_in[1];
    const float* vec1   = (const float*)d_in[2];
    const float* vec0   = (const float*)d_in[3];
    const float* Wp     = (const float*)d_in[4];
    const float* bp     = (const float*)d_in[5];
    const float* a_leaf = (const float*)d_in[6];
    const float* Wb2    = (const float*)d_in[7];
    const float* bb2    = (const float*)d_in[8];
    const float* a2     = (const float*)d_in[9];
    const float* Wb1    = (const float*)d_in[10];
    const float* bb1    = (const float*)d_in[11];
    const float* Ws1    = (const float*)d_in[12];
    const float* bs1    = (const float*)d_in[13];
    const float* a1     = (const float*)d_in[14];
    const float* Wb0    = (const float*)d_in[15];
    const float* bb0    = (const float*)d_in[16];
    const float* Ws0    = (const float*)d_in[17];
    const float* bs0    = (const float*)d_in[18];
    const float* a0     = (const float*)d_in[19];
    const int*   cl2    = (const int*)d_in[20];
    const int*   cr2    = (const int*)d_in[21];
    const int*   cl1    = (const int*)d_in[22];
    const int*   cr1    = (const int*)d_in[23];
    const int*   cs1    = (const int*)d_in[24];
    const int*   cl0    = (const int*)d_in[25];
    const int*   cr0    = (const int*)d_in[26];
    const int*   cs0    = (const int*)d_in[27];

    const int B  = out_size / DIM;          // 8
    const int N3 = in_sizes[0] / (3 * B);   // 131072
    const int N2 = in_sizes[1] / (3 * B);   // 65536
    const int N1 = in_sizes[2] / (3 * B);   // 1024

    // cluster size 16 is non-portable on sm_100a; enable it (idempotent, cheap)
    cudaFuncSetAttribute(encoder_fused_kernel,
                         cudaFuncAttributeNonPortableClusterSizeAllowed, 1);

    encoder_fused_kernel<<<B * NSLICE, NTHREADS>>>(
        points, vec2, vec1, vec0,
        Wp, bp, a_leaf, Wb2, bb2, a2,
        Wb1, bb1, Ws1, bs1, a1,
        Wb0, bb0, Ws0, bs0, a0,
        cl2, cr2, cl1, cr1, cs1, cl0, cr0, cs0,
        (float*)d_out, N3, N2, N1);
}

// round 9
// speedup vs baseline: 1.1870x; 1.1870x over previous
#include <cuda_runtime.h>
#include <cstdint>

#define DIM 128
#define NSLICE 16          // k-slices per batch
#define NTHREADS 256       // 8 warps per block
#define NBATCH 8

// ---------------- global scratch (static __device__, no allocation) ----------------
__device__ float g_h2[NBATCH][5][DIM];
__device__ float g_tb[NBATCH][2][DIM];
__device__ float g_h1[NBATCH][2][DIM];
__device__ float g_tb0[NBATCH][DIM];

// per-batch flag array: one word per block, all 16 words in one 64B span
// (parallel stores, single-sector poll). Padded to 128B per batch.
struct __align__(128) FlagLine { unsigned f[NSLICE]; unsigned pad[32 - NSLICE]; };
__device__ FlagLine g_flags[NBATCH];

__device__ __forceinline__ float prelu_f(float x, float a) {
    return x >= 0.0f ? x : a * x;
}

// xor-butterfly: full sum in EVERY lane
__device__ __forceinline__ float wred(float v) {
    v += __shfl_xor_sync(0xffffffffu, v, 16);
    v += __shfl_xor_sync(0xffffffffu, v, 8);
    v += __shfl_xor_sync(0xffffffffu, v, 4);
    v += __shfl_xor_sync(0xffffffffu, v, 2);
    v += __shfl_xor_sync(0xffffffffu, v, 1);
    return v;
}

__device__ __forceinline__ float dot4(float4 a, float4 b) {
    return fmaf(a.x, b.x, fmaf(a.y, b.y, fmaf(a.z, b.z, a.w * b.w)));
}

// flag barrier: store own flag (release), lanes 0..15 of warp 0 poll all 16 flags
// (acquire) until every one has reached `target`. No atomics, no serialization.
__device__ __forceinline__ void flag_bar(int b, int s, unsigned target,
                                         int w, int l) {
    __syncthreads();                       // all warps' phase stores done (cta fence)
    if (w == 0) {
        if (l == 0) {
            asm volatile("st.release.gpu.global.u32 [%0], %1;"
                         :: "l"(&g_flags[b].f[s]), "r"(target) : "memory");
        }
        unsigned my = target;              // own flag trivially satisfied
        for (;;) {
            unsigned fv = my;
            if (l < NSLICE) {
                asm volatile("ld.acquire.gpu.global.u32 %0, [%1];"
                             : "=r"(fv) : "l"(&g_flags[b].f[l]) : "memory");
            }
            if (__all_sync(0xffffffffu, (int)(fv - target) >= 0)) break;
        }
    }
    __syncthreads();                       // broadcast release to all warps
}

__global__ __launch_bounds__(NTHREADS, 1) void encoder_fused_kernel(
    const float* __restrict__ points,  // [B, N3, 3]
    const float* __restrict__ vec2,    // [B, N2, 3]
    const float* __restrict__ vec1,    // [B, N1, 3]
    const float* __restrict__ vec0,    // [B, 1, 3]
    const float* __restrict__ Wp,      // [DIM, 3]
    const float* __restrict__ bp,
    const float* __restrict__ a_leaf,
    const float* __restrict__ Wb2, const float* __restrict__ bb2,
    const float* __restrict__ a2p,
    const float* __restrict__ Wb1, const float* __restrict__ bb1,
    const float* __restrict__ Ws1, const float* __restrict__ bs1,
    const float* __restrict__ a1p,
    const float* __restrict__ Wb0, const float* __restrict__ bb0,
    const float* __restrict__ Ws0, const float* __restrict__ bs0,
    const float* __restrict__ a0p,
    const int* __restrict__ cl2, const int* __restrict__ cr2,
    const int* __restrict__ cl1, const int* __restrict__ cr1,
    const int* __restrict__ cs1,
    const int* __restrict__ cl0, const int* __restrict__ cr0,
    const int* __restrict__ cs0,
    float* __restrict__ out,           // [B, DIM]
    int N3, int N2n, int N1n)
{
    const int b   = blockIdx.x >> 4;
    const int s   = blockIdx.x & (NSLICE - 1);
    const int tid = threadIdx.x;
    const int w   = tid >> 5, l = tid & 31;

    // replay-safe monotonic base: own flag's value from previous replay
    // (identical across blocks of a batch; 0 on first run)
    unsigned base = 0;
    if (tid == 0) base = g_flags[b].f[s];
    base = __shfl_sync(0xffffffffu, base, 0);
    base = __ballot_sync(0xffffffffu, true) ? base : 0u;  // keep in all warps via smem below

    __shared__ unsigned sbase;
    if (tid == 0) sbase = base;

    // ---------------- register-preload ALL weight slices (no dependencies) ----------------
    const int kB  = (s << 3) + w;           // phase B/E/F channel
    const int idx = (s << 4) + (w << 1);    // phase C/D pair base
    const int jCD = idx >> 7;
    const int k0  = idx & 127, k1 = k0 + 1;

    float4 wB[6], wC0[6], wC1[6], wE[6];
    float4 wD0[2], wD1[2], wF[2];
    {
        const float4* p1 = (const float4*)Wb2 + (long)kB * 192;
        const float4* p2 = (const float4*)Wb1 + (long)k0 * 192;
        const float4* p3 = (const float4*)Wb1 + (long)k1 * 192;
        const float4* p4 = (const float4*)Wb0 + (long)kB * 192;
        #pragma unroll
        for (int t = 0; t < 6; t++) {
            wB[t]  = p1[t * 32 + l];
            wC0[t] = p2[t * 32 + l];
            wC1[t] = p3[t * 32 + l];
            wE[t]  = p4[t * 32 + l];
        }
        const float4* p5 = (const float4*)Ws1 + (long)k0 * 64;
        const float4* p6 = (const float4*)Ws1 + (long)k1 * 64;
        const float4* p7 = (const float4*)Ws0 + (long)kB * 64;
        wD0[0] = p5[l]; wD0[1] = p5[32 + l];
        wD1[0] = p6[l]; wD1[1] = p6[32 + l];
        wF[0]  = p7[l]; wF[1]  = p7[32 + l];
    }
    const float bB  = bb2[kB];
    const float bC0 = bb1[k0], bC1 = bb1[k1];
    const float bD0 = bs1[k0], bD1 = bs1[k1];
    const float bE  = bb0[kB], bF = bs0[kB];
    const float AL = a_leaf[0], A2 = a2p[0], A1 = a1p[0], A0 = a0p[0];

    __shared__ int sp[12], sn2[5], sl1[2];
    __shared__ __align__(16) float svec2[5][3];
    __shared__ __align__(16) float svec1[2][3];
    __shared__ __align__(16) float svec0[3];
    __shared__ __align__(16) float leaf[12][DIM];
    __shared__ __align__(16) float zbuf[5 * 768];   // z2 -> z1 -> z0 (reused)
    __shared__ __align__(16) float h2all[5][DIM];
    __shared__ __align__(16) float tbs[2][DIM];
    __shared__ __align__(16) float h1all[2][DIM];
    __shared__ __align__(16) float tb0s[DIM];

    // ---- resolve the (batch-invariant) dependency cone ----
    if (tid == 0) {
        int l1a = cl0[0];
        int l1b = cr0[0];
        sl1[0] = l1a; sl1[1] = l1b;
        int n0 = cl1[l1a], n1 = cr1[l1a], n2_ = cl1[l1b], n3 = cr1[l1b], n4 = cs0[0];
        sn2[0] = n0; sn2[1] = n1; sn2[2] = n2_; sn2[3] = n3; sn2[4] = n4;
        sp[0] = cl2[n0];  sp[1] = cr2[n0];
        sp[2] = cl2[n1];  sp[3] = cr2[n1];
        sp[4] = cl2[n2_]; sp[5] = cr2[n2_];
        sp[6] = cl2[n3];  sp[7] = cr2[n3];
        sp[8] = cl2[n4];  sp[9] = cr2[n4];
        sp[10] = cs1[l1a]; sp[11] = cs1[l1b];
    }
    __syncthreads();
    base = sbase;

    // ---- preload vec gathers into smem ----
    if (tid < 15) {
        int j = tid / 3, v = tid - 3 * j;
        svec2[j][v] = vec2[((long)b * N2n + sn2[j]) * 3 + v];
    } else if (tid < 21) {
        int t = tid - 15;
        int j = t / 3, v = t - 3 * j;
        svec1[j][v] = vec1[((long)b * N1n + sl1[j]) * 3 + v];
    } else if (tid < 24) {
        svec0[tid - 21] = vec0[(long)b * 3 + (tid - 21)];
    }

    // ---- leaves: 12 rows, h3 = prelu(points @ Wp^T + bp) ----
    for (int i = tid; i < 12 * DIM; i += NTHREADS) {
        int j = i >> 7, k = i & 127;
        const float* pt = points + ((long)b * N3 + sp[j]) * 3;
        float h = fmaf(Wp[k * 3 + 0], pt[0],
                  fmaf(Wp[k * 3 + 1], pt[1],
                  fmaf(Wp[k * 3 + 2], pt[2], bp[k])));
        leaf[j][k] = prelu_f(h, AL);
    }
    __syncthreads();

    // ---- z2 build (smem-only) ----
    for (int i = tid; i < 5 * 768; i += NTHREADS) {
        int j = i / 768;
        int e = i - j * 768;
        unsigned d = (unsigned)e / 3u;
        int v = e - 3 * (int)d;
        zbuf[i] = leaf[2 * j + (d >> 7)][d & 127] * svec2[j][v];
    }
    __syncthreads();

    // ---- Phase B: layer-2 bilinear, weights in regs ----
    {
        const float4* zr = (const float4*)zbuf;
        float acc[5] = {0.f, 0.f, 0.f, 0.f, 0.f};
        #pragma unroll
        for (int t = 0; t < 6; t++) {
            #pragma unroll
            for (int j = 0; j < 5; j++)
                acc[j] += dot4(wB[t], zr[j * 192 + t * 32 + l]);
        }
        #pragma unroll
        for (int j = 0; j < 5; j++) {
            float r = wred(acc[j]);
            if (l == 0) g_h2[b][j][kB] = prelu_f(r + bB, A2);
        }
    }
    flag_bar(b, s, base + 1u, w, l);

    // ---- load h2 (one coalesced L2 round), build z1 ----
    for (int i = tid; i < 5 * DIM; i += NTHREADS)
        h2all[i >> 7][i & 127] = g_h2[b][i >> 7][i & 127];
    __syncthreads();
    for (int i = tid; i < 2 * 768; i += NTHREADS) {
        int j = i >= 768 ? 1 : 0;
        int e = i - j * 768;
        unsigned d = (unsigned)e / 3u;
        int v = e - 3 * (int)d;
        zbuf[i] = h2all[2 * j + (d >> 7)][d & 127] * svec1[j][v];
    }
    __syncthreads();

    // ---- Phase C: layer-1 bilinear, weights in regs ----
    {
        const float4* zr = (const float4*)(zbuf + jCD * 768);
        float a0 = 0.f, a1 = 0.f;
        #pragma unroll
        for (int t = 0; t < 6; t++) {
            float4 zz = zr[t * 32 + l];
            a0 += dot4(wC0[t], zz);
            a1 += dot4(wC1[t], zz);
        }
        float r0 = wred(a0), r1 = wred(a1);
        if (l == 0)      g_tb[b][jCD][k0] = prelu_f(r0 + bC0, A1);
        else if (l == 1) g_tb[b][jCD][k1] = prelu_f(r1 + bC1, A1);
    }
    flag_bar(b, s, base + 2u, w, l);

    // ---- load tb, Phase D: sample-merge linear, weights in regs ----
    for (int i = tid; i < 2 * DIM; i += NTHREADS)
        tbs[i >> 7][i & 127] = g_tb[b][i >> 7][i & 127];
    __syncthreads();
    {
        float4 xa = ((const float4*)tbs[jCD])[l];
        float4 xb = ((const float4*)leaf[10 + jCD])[l];
        float a0 = dot4(wD0[0], xa) + dot4(wD0[1], xb);
        float a1 = dot4(wD1[0], xa) + dot4(wD1[1], xb);
        float r0 = wred(a0), r1 = wred(a1);
        if (l == 0)      g_h1[b][jCD][k0] = prelu_f(r0 + bD0, A1);
        else if (l == 1) g_h1[b][jCD][k1] = prelu_f(r1 + bD1, A1);
    }
    flag_bar(b, s, base + 3u, w, l);

    // ---- load h1, build z0 ----
    for (int i = tid; i < 2 * DIM; i += NTHREADS)
        h1all[i >> 7][i & 127] = g_h1[b][i >> 7][i & 127];
    __syncthreads();
    for (int e = tid; e < 768; e += NTHREADS) {
        unsigned d = (unsigned)e / 3u;
        int v = e - 3 * (int)d;
        zbuf[e] = h1all[d >> 7][d & 127] * svec0[v];
    }
    __syncthreads();

    // ---- Phase E: root bilinear, weights in regs ----
    {
        const float4* zr = (const float4*)zbuf;
        float acc = 0.f;
        #pragma unroll
        for (int t = 0; t < 6; t++)
            acc += dot4(wE[t], zr[t * 32 + l]);
        float r = wred(acc);
        if (l == 0) g_tb0[b][kB] = prelu_f(r + bE, A0);
    }
    flag_bar(b, s, base + 4u, w, l);

    // ---- load tb0, Phase F: root linear, weights in regs ----
    if (tid < DIM) tb0s[tid] = g_tb0[b][tid];
    __syncthreads();
    {
        float acc = dot4(wF[0], ((const float4*)tb0s)[l]);
        acc      += dot4(wF[1], ((const float4*)h2all[4])[l]);
        float r = wred(acc);
        if (l == 0) out[(long)b * DIM + kB] = prelu_f(r + bF, A0);
    }
}

extern "C" void kernel_launch(void* const* d_in, const int* in_sizes, int n_in,
                              void* d_out, int out_size)
{
    const float* points = (const float*)d_in[0];
    const float* vec2   = (const float*)d_in[1];
    const float* vec1   = (const float*)d_in[2];
    const float* vec0   = (const float*)d_in[3];
    const float* Wp     = (const float*)d_in[4];
    const float* bp     = (const float*)d_in[5];
    const float* a_leaf = (const float*)d_in[6];
    const float* Wb2    = (const float*)d_in[7];
    const float* bb2    = (const float*)d_in[8];
    const float* a2     = (const float*)d_in[9];
    const float* Wb1    = (const float*)d_in[10];
    const float* bb1    = (const float*)d_in[11];
    const float* Ws1    = (const float*)d_in[12];
    const float* bs1    = (const float*)d_in[13];
    const float* a1     = (const float*)d_in[14];
    const float* Wb0    = (const float*)d_in[15];
    const float* bb0    = (const float*)d_in[16];
    const float* Ws0    = (const float*)d_in[17];
    const float* bs0    = (const float*)d_in[18];
    const float* a0     = (const float*)d_in[19];
    const int*   cl2    = (const int*)d_in[20];
    const int*   cr2    = (const int*)d_in[21];
    const int*   cl1    = (const int*)d_in[22];
    const int*   cr1    = (const int*)d_in[23];
    const int*   cs1    = (const int*)d_in[24];
    const int*   cl0    = (const int*)d_in[25];
    const int*   cr0    = (const int*)d_in[26];
    const int*   cs0    = (const int*)d_in[27];

    const int B  = out_size / DIM;          // 8
    const int N3 = in_sizes[0] / (3 * B);   // 131072
    const int N2 = in_sizes[1] / (3 * B);   // 65536
    const int N1 = in_sizes[2] / (3 * B);   // 1024

    encoder_fused_kernel<<<B * NSLICE, NTHREADS>>>(
        points, vec2, vec1, vec0,
        Wp, bp, a_leaf, Wb2, bb2, a2,
        Wb1, bb1, Ws1, bs1, a1,
        Wb0, bb0, Ws0, bs0, a0,
        cl2, cr2, cl1, cr1, cs1, cl0, cr0, cs0,
        (float*)d_out, N3, N2, N1);
}

// round 10
// speedup vs baseline: 1.3403x; 1.1291x over previous
#include <cuda_runtime.h>
#include <cstdint>

#define DIM 128
#define NSLICE 16          // k-slices per batch
#define NTHREADS 256       // 8 warps per block
#define NBATCH 8

// ---------------- global scratch (static __device__, no allocation) ----------------
__device__ float g_h2[NBATCH][5][DIM];
__device__ float g_tb[NBATCH][2][DIM];
__device__ float g_h1[NBATCH][2][DIM];
__device__ float g_tb0[NBATCH][DIM];

// per-(batch,phase) barrier: ONE monotonic counter, own 128B line
struct __align__(128) BarSlot { unsigned c; unsigned pad[31]; };
__device__ BarSlot g_bar[NBATCH * 4];

__device__ __forceinline__ float prelu_f(float x, float a) {
    return x >= 0.0f ? x : a * x;
}

// xor-butterfly: full sum in EVERY lane
__device__ __forceinline__ float wred(float v) {
    v += __shfl_xor_sync(0xffffffffu, v, 16);
    v += __shfl_xor_sync(0xffffffffu, v, 8);
    v += __shfl_xor_sync(0xffffffffu, v, 4);
    v += __shfl_xor_sync(0xffffffffu, v, 2);
    v += __shfl_xor_sync(0xffffffffu, v, 1);
    return v;
}

__device__ __forceinline__ float dot4(float4 a, float4 b) {
    return fmaf(a.x, b.x, fmaf(a.y, b.y, fmaf(a.z, b.z, a.w * b.w)));
}

// barrier: fire-and-forget RED arrival (release), poll single counter (acquire)
// until it reaches the precomputed, replay-safe target.
__device__ __forceinline__ void red_bar(int slot, unsigned target) {
    __syncthreads();                       // CTA-level hb: all warps' stores ordered
    if (threadIdx.x == 0) {
        unsigned* cp = &g_bar[slot].c;
        asm volatile("red.release.gpu.global.add.u32 [%0], %1;"
                     :: "l"(cp), "r"(1u) : "memory");
        unsigned cur;
        do {
            asm volatile("ld.acquire.gpu.global.u32 %0, [%1];"
                         : "=r"(cur) : "l"(cp) : "memory");
        } while ((int)(cur - target) < 0);  // wrap-safe
    }
    __syncthreads();
}

__global__ __launch_bounds__(NTHREADS, 1) void encoder_fused_kernel(
    const float* __restrict__ points,  // [B, N3, 3]
    const float* __restrict__ vec2,    // [B, N2, 3]
    const float* __restrict__ vec1,    // [B, N1, 3]
    const float* __restrict__ vec0,    // [B, 1, 3]
    const float* __restrict__ Wp,      // [DIM, 3]
    const float* __restrict__ bp,
    const float* __restrict__ a_leaf,
    const float* __restrict__ Wb2, const float* __restrict__ bb2,
    const float* __restrict__ a2p,
    const float* __restrict__ Wb1, const float* __restrict__ bb1,
    const float* __restrict__ Ws1, const float* __restrict__ bs1,
    const float* __restrict__ a1p,
    const float* __restrict__ Wb0, const float* __restrict__ bb0,
    const float* __restrict__ Ws0, const float* __restrict__ bs0,
    const float* __restrict__ a0p,
    const int* __restrict__ cl2, const int* __restrict__ cr2,
    const int* __restrict__ cl1, const int* __restrict__ cr1,
    const int* __restrict__ cs1,
    const int* __restrict__ cl0, const int* __restrict__ cr0,
    const int* __restrict__ cs0,
    float* __restrict__ out,           // [B, DIM]
    int N3, int N2n, int N1n)
{
    const int b   = blockIdx.x >> 4;
    const int s   = blockIdx.x & (NSLICE - 1);
    const int tid = threadIdx.x;
    const int w   = tid >> 5, l = tid & 31;

    // ---- precompute replay-safe barrier targets (thread 0; overlaps cone chain) ----
    // phase p>0: no current-replay arrivals can precede this read -> v = 16R.
    // phase 0:  v in [16R, 16R+15]. Either way (v/16)*16 + 16 is this replay's target.
    unsigned tgt0 = 0, tgt1 = 0, tgt2 = 0, tgt3 = 0;
    if (tid == 0) {
        unsigned v;
        asm volatile("ld.acquire.gpu.global.u32 %0, [%1];" : "=r"(v) : "l"(&g_bar[b*4+0].c));
        tgt0 = (v / NSLICE) * NSLICE + NSLICE;
        asm volatile("ld.acquire.gpu.global.u32 %0, [%1];" : "=r"(v) : "l"(&g_bar[b*4+1].c));
        tgt1 = (v / NSLICE) * NSLICE + NSLICE;
        asm volatile("ld.acquire.gpu.global.u32 %0, [%1];" : "=r"(v) : "l"(&g_bar[b*4+2].c));
        tgt2 = (v / NSLICE) * NSLICE + NSLICE;
        asm volatile("ld.acquire.gpu.global.u32 %0, [%1];" : "=r"(v) : "l"(&g_bar[b*4+3].c));
        tgt3 = (v / NSLICE) * NSLICE + NSLICE;
    }

    // ---------------- register-preload ALL weight slices (no dependencies) ----------------
    const int kB  = (s << 3) + w;           // phase B/E/F channel
    const int idx = (s << 4) + (w << 1);    // phase C/D pair base
    const int jCD = idx >> 7;
    const int k0  = idx & 127, k1 = k0 + 1;

    float4 wB[6], wC0[6], wC1[6], wE[6];
    float4 wD0[2], wD1[2], wF[2];
    {
        const float4* p1 = (const float4*)Wb2 + (long)kB * 192;
        const float4* p2 = (const float4*)Wb1 + (long)k0 * 192;
        const float4* p3 = (const float4*)Wb1 + (long)k1 * 192;
        const float4* p4 = (const float4*)Wb0 + (long)kB * 192;
        #pragma unroll
        for (int t = 0; t < 6; t++) {
            wB[t]  = p1[t * 32 + l];
            wC0[t] = p2[t * 32 + l];
            wC1[t] = p3[t * 32 + l];
            wE[t]  = p4[t * 32 + l];
        }
        const float4* p5 = (const float4*)Ws1 + (long)k0 * 64;
        const float4* p6 = (const float4*)Ws1 + (long)k1 * 64;
        const float4* p7 = (const float4*)Ws0 + (long)kB * 64;
        wD0[0] = p5[l]; wD0[1] = p5[32 + l];
        wD1[0] = p6[l]; wD1[1] = p6[32 + l];
        wF[0]  = p7[l]; wF[1]  = p7[32 + l];
    }
    const float bB  = bb2[kB];
    const float bC0 = bb1[k0], bC1 = bb1[k1];
    const float bD0 = bs1[k0], bD1 = bs1[k1];
    const float bE  = bb0[kB], bF = bs0[kB];
    const float AL = a_leaf[0], A2 = a2p[0], A1 = a1p[0], A0 = a0p[0];

    __shared__ int sp[12], sn2[5], sl1[2];
    __shared__ __align__(16) float svec2[5][3];
    __shared__ __align__(16) float svec1[2][3];
    __shared__ __align__(16) float svec0[3];
    __shared__ __align__(16) float leaf[12][DIM];
    __shared__ __align__(16) float zbuf[5 * 768];   // z2 -> z1 -> z0 (reused)
    __shared__ __align__(16) float h2all[5][DIM];
    __shared__ __align__(16) float tbs[2][DIM];
    __shared__ __align__(16) float h1all[2][DIM];
    __shared__ __align__(16) float tb0s[DIM];

    // ---- resolve the (batch-invariant) dependency cone ----
    if (tid == 0) {
        int l1a = cl0[0];
        int l1b = cr0[0];
        sl1[0] = l1a; sl1[1] = l1b;
        int n0 = cl1[l1a], n1 = cr1[l1a], n2_ = cl1[l1b], n3 = cr1[l1b], n4 = cs0[0];
        sn2[0] = n0; sn2[1] = n1; sn2[2] = n2_; sn2[3] = n3; sn2[4] = n4;
        sp[0] = cl2[n0];  sp[1] = cr2[n0];
        sp[2] = cl2[n1];  sp[3] = cr2[n1];
        sp[4] = cl2[n2_]; sp[5] = cr2[n2_];
        sp[6] = cl2[n3];  sp[7] = cr2[n3];
        sp[8] = cl2[n4];  sp[9] = cr2[n4];
        sp[10] = cs1[l1a]; sp[11] = cs1[l1b];
    }
    __syncthreads();

    // ---- preload vec gathers into smem ----
    if (tid < 15) {
        int j = tid / 3, v = tid - 3 * j;
        svec2[j][v] = vec2[((long)b * N2n + sn2[j]) * 3 + v];
    } else if (tid < 21) {
        int t = tid - 15;
        int j = t / 3, v = t - 3 * j;
        svec1[j][v] = vec1[((long)b * N1n + sl1[j]) * 3 + v];
    } else if (tid < 24) {
        svec0[tid - 21] = vec0[(long)b * 3 + (tid - 21)];
    }

    // ---- leaves: 12 rows, h3 = prelu(points @ Wp^T + bp) ----
    for (int i = tid; i < 12 * DIM; i += NTHREADS) {
        int j = i >> 7, k = i & 127;
        const float* pt = points + ((long)b * N3 + sp[j]) * 3;
        float h = fmaf(Wp[k * 3 + 0], pt[0],
                  fmaf(Wp[k * 3 + 1], pt[1],
                  fmaf(Wp[k * 3 + 2], pt[2], bp[k])));
        leaf[j][k] = prelu_f(h, AL);
    }
    __syncthreads();

    // ---- z2 build (smem-only) ----
    for (int i = tid; i < 5 * 768; i += NTHREADS) {
        int j = i / 768;
        int e = i - j * 768;
        unsigned d = (unsigned)e / 3u;
        int v = e - 3 * (int)d;
        zbuf[i] = leaf[2 * j + (d >> 7)][d & 127] * svec2[j][v];
    }
    __syncthreads();

    // ---- Phase B: layer-2 bilinear, weights in regs ----
    {
        const float4* zr = (const float4*)zbuf;
        float acc[5] = {0.f, 0.f, 0.f, 0.f, 0.f};
        #pragma unroll
        for (int t = 0; t < 6; t++) {
            #pragma unroll
            for (int j = 0; j < 5; j++)
                acc[j] += dot4(wB[t], zr[j * 192 + t * 32 + l]);
        }
        #pragma unroll
        for (int j = 0; j < 5; j++) {
            float r = wred(acc[j]);
            if (l == 0) g_h2[b][j][kB] = prelu_f(r + bB, A2);
        }
    }
    red_bar(b * 4 + 0, tgt0);

    // ---- load h2 (one coalesced L2 round), build z1 ----
    for (int i = tid; i < 5 * DIM; i += NTHREADS)
        h2all[i >> 7][i & 127] = g_h2[b][i >> 7][i & 127];
    __syncthreads();
    for (int i = tid; i < 2 * 768; i += NTHREADS) {
        int j = i >= 768 ? 1 : 0;
        int e = i - j * 768;
        unsigned d = (unsigned)e / 3u;
        int v = e - 3 * (int)d;
        zbuf[i] = h2all[2 * j + (d >> 7)][d & 127] * svec1[j][v];
    }
    __syncthreads();

    // ---- Phase C: layer-1 bilinear, weights in regs ----
    {
        const float4* zr = (const float4*)(zbuf + jCD * 768);
        float a0 = 0.f, a1 = 0.f;
        #pragma unroll
        for (int t = 0; t < 6; t++) {
            float4 zz = zr[t * 32 + l];
            a0 += dot4(wC0[t], zz);
            a1 += dot4(wC1[t], zz);
        }
        float r0 = wred(a0), r1 = wred(a1);
        if (l == 0)      g_tb[b][jCD][k0] = prelu_f(r0 + bC0, A1);
        else if (l == 1) g_tb[b][jCD][k1] = prelu_f(r1 + bC1, A1);
    }
    red_bar(b * 4 + 1, tgt1);

    // ---- load tb, Phase D: sample-merge linear, weights in regs ----
    for (int i = tid; i < 2 * DIM; i += NTHREADS)
        tbs[i >> 7][i & 127] = g_tb[b][i >> 7][i & 127];
    __syncthreads();
    {
        float4 xa = ((const float4*)tbs[jCD])[l];
        float4 xb = ((const float4*)leaf[10 + jCD])[l];
        float a0 = dot4(wD0[0], xa) + dot4(wD0[1], xb);
        float a1 = dot4(wD1[0], xa) + dot4(wD1[1], xb);
        float r0 = wred(a0), r1 = wred(a1);
        if (l == 0)      g_h1[b][jCD][k0] = prelu_f(r0 + bD0, A1);
        else if (l == 1) g_h1[b][jCD][k1] = prelu_f(r1 + bD1, A1);
    }
    red_bar(b * 4 + 2, tgt2);

    // ---- load h1, build z0 ----
    for (int i = tid; i < 2 * DIM; i += NTHREADS)
        h1all[i >> 7][i & 127] = g_h1[b][i >> 7][i & 127];
    __syncthreads();
    for (int e = tid; e < 768; e += NTHREADS) {
        unsigned d = (unsigned)e / 3u;
        int v = e - 3 * (int)d;
        zbuf[e] = h1all[d >> 7][d & 127] * svec0[v];
    }
    __syncthreads();

    // ---- Phase E: root bilinear, weights in regs ----
    {
        const float4* zr = (const float4*)zbuf;
        float acc = 0.f;
        #pragma unroll
        for (int t = 0; t < 6; t++)
            acc += dot4(wE[t], zr[t * 32 + l]);
        float r = wred(acc);
        if (l == 0) g_tb0[b][kB] = prelu_f(r + bE, A0);
    }
    red_bar(b * 4 + 3, tgt3);

    // ---- load tb0, Phase F: root linear, weights in regs ----
    if (tid < DIM) tb0s[tid] = g_tb0[b][tid];
    __syncthreads();
    {
        float acc = dot4(wF[0], ((const float4*)tb0s)[l]);
        acc      += dot4(wF[1], ((const float4*)h2all[4])[l]);
        float r = wred(acc);
        if (l == 0) out[(long)b * DIM + kB] = prelu_f(r + bF, A0);
    }
}

extern "C" void kernel_launch(void* const* d_in, const int* in_sizes, int n_in,
                              void* d_out, int out_size)
{
    const float* points = (const float*)d_in[0];
    const float* vec2   = (const float*)d_in[1];
    const float* vec1   = (const float*)d_in[2];
    const float* vec0   = (const float*)d_in[3];
    const float* Wp     = (const float*)d_in[4];
    const float* bp     = (const float*)d_in[5];
    const float* a_leaf = (const float*)d_in[6];
    const float* Wb2    = (const float*)d_in[7];
    const float* bb2    = (const float*)d_in[8];
    const float* a2     = (const float*)d_in[9];
    const float* Wb1    = (const float*)d_in[10];
    const float* bb1    = (const float*)d_in[11];
    const float* Ws1    = (const float*)d_in[12];
    const float* bs1    = (const float*)d_in[13];
    const float* a1     = (const float*)d_in[14];
    const float* Wb0    = (const float*)d_in[15];
    const float* bb0    = (const float*)d_in[16];
    const float* Ws0    = (const float*)d_in[17];
    const float* bs0    = (const float*)d_in[18];
    const float* a0     = (const float*)d_in[19];
    const int*   cl2    = (const int*)d_in[20];
    const int*   cr2    = (const int*)d_in[21];
    const int*   cl1    = (const int*)d_in[22];
    const int*   cr1    = (const int*)d_in[23];
    const int*   cs1    = (const int*)d_in[24];
    const int*   cl0    = (const int*)d_in[25];
    const int*   cr0    = (const int*)d_in[26];
    const int*   cs0    = (const int*)d_in[27];

    const int B  = out_size / DIM;          // 8
    const int N3 = in_sizes[0] / (3 * B);   // 131072
    const int N2 = in_sizes[1] / (3 * B);   // 65536
    const int N1 = in_sizes[2] / (3 * B);   // 1024

    encoder_fused_kernel<<<B * NSLICE, NTHREADS>>>(
        points, vec2, vec1, vec0,
        Wp, bp, a_leaf, Wb2, bb2, a2,
        Wb1, bb1, Ws1, bs1, a1,
        Wb0, bb0, Ws0, bs0, a0,
        cl2, cr2, cl1, cr1, cs1, cl0, cr0, cs0,
        (float*)d_out, N3, N2, N1);
}

// round 11
// speedup vs baseline: 1.4971x; 1.1170x over previous
#include <cuda_runtime.h>
#include <cstdint>

#define DIM 128
#define NSLICE 16          // k-slices per batch
#define NTHREADS 256       // 8 warps per block
#define NBATCH 8

// ---------------- global scratch (static __device__, no allocation) ----------------
// NOTE: row adjacency is load-bearing: h2[2j]||h2[2j+1] and h1[0]||h1[1] are read
// as 256 contiguous floats by the d-contiguous lanes.
__device__ float g_h2[NBATCH][5][DIM];
__device__ float g_tb[NBATCH][2][DIM];
__device__ float g_h1[NBATCH][2][DIM];
__device__ float g_tb0[NBATCH][DIM];

// per-(batch,phase) barrier: ONE monotonic counter, own 128B line
struct __align__(128) BarSlot { unsigned c; unsigned pad[31]; };
__device__ BarSlot g_bar[NBATCH * 4];

__device__ __forceinline__ float prelu_f(float x, float a) {
    return x >= 0.0f ? x : a * x;
}

// xor-butterfly: full sum in EVERY lane
__device__ __forceinline__ float wred(float v) {
    v += __shfl_xor_sync(0xffffffffu, v, 16);
    v += __shfl_xor_sync(0xffffffffu, v, 8);
    v += __shfl_xor_sync(0xffffffffu, v, 4);
    v += __shfl_xor_sync(0xffffffffu, v, 2);
    v += __shfl_xor_sync(0xffffffffu, v, 1);
    return v;
}

// barrier: fire-and-forget RED arrival (release), poll single counter (acquire)
// until it reaches the precomputed, replay-safe target.
__device__ __forceinline__ void red_bar(int slot, unsigned target) {
    __syncthreads();
    if (threadIdx.x == 0) {
        unsigned* cp = &g_bar[slot].c;
        asm volatile("red.release.gpu.global.add.u32 [%0], %1;"
                     :: "l"(cp), "r"(1u) : "memory");
        unsigned cur;
        do {
            asm volatile("ld.acquire.gpu.global.u32 %0, [%1];"
                         : "=r"(cur) : "l"(cp) : "memory");
        } while ((int)(cur - target) < 0);
    }
    __syncthreads();
}

// load 8 consecutive floats (32B-aligned) into x[8]
__device__ __forceinline__ void ld8(const float* p, float* x) {
    float4 a = ((const float4*)p)[0];
    float4 b = ((const float4*)p)[1];
    x[0]=a.x; x[1]=a.y; x[2]=a.z; x[3]=a.w;
    x[4]=b.x; x[5]=b.y; x[6]=b.z; x[7]=b.w;
}

__global__ __launch_bounds__(NTHREADS, 1) void encoder_fused_kernel(
    const float* __restrict__ points,  // [B, N3, 3]
    const float* __restrict__ vec2,    // [B, N2, 3]
    const float* __restrict__ vec1,    // [B, N1, 3]
    const float* __restrict__ vec0,    // [B, 1, 3]
    const float* __restrict__ Wp,      // [DIM, 3]
    const float* __restrict__ bp,
    const float* __restrict__ a_leaf,
    const float* __restrict__ Wb2, const float* __restrict__ bb2,
    const float* __restrict__ a2p,
    const float* __restrict__ Wb1, const float* __restrict__ bb1,
    const float* __restrict__ Ws1, const float* __restrict__ bs1,
    const float* __restrict__ a1p,
    const float* __restrict__ Wb0, const float* __restrict__ bb0,
    const float* __restrict__ Ws0, const float* __restrict__ bs0,
    const float* __restrict__ a0p,
    const int* __restrict__ cl2, const int* __restrict__ cr2,
    const int* __restrict__ cl1, const int* __restrict__ cr1,
    const int* __restrict__ cs1,
    const int* __restrict__ cl0, const int* __restrict__ cr0,
    const int* __restrict__ cs0,
    float* __restrict__ out,           // [B, DIM]
    int N3, int N2n, int N1n)
{
    const int b   = blockIdx.x >> 4;
    const int s   = blockIdx.x & (NSLICE - 1);
    const int tid = threadIdx.x;
    const int w   = tid >> 5, l = tid & 31;

    // ---- precompute replay-safe barrier targets (thread 0; overlaps preload) ----
    unsigned tgt0 = 0, tgt1 = 0, tgt2 = 0, tgt3 = 0;
    if (tid == 0) {
        unsigned v;
        asm volatile("ld.acquire.gpu.global.u32 %0, [%1];" : "=r"(v) : "l"(&g_bar[b*4+0].c));
        tgt0 = (v / NSLICE) * NSLICE + NSLICE;
        asm volatile("ld.acquire.gpu.global.u32 %0, [%1];" : "=r"(v) : "l"(&g_bar[b*4+1].c));
        tgt1 = (v / NSLICE) * NSLICE + NSLICE;
        asm volatile("ld.acquire.gpu.global.u32 %0, [%1];" : "=r"(v) : "l"(&g_bar[b*4+2].c));
        tgt2 = (v / NSLICE) * NSLICE + NSLICE;
        asm volatile("ld.acquire.gpu.global.u32 %0, [%1];" : "=r"(v) : "l"(&g_bar[b*4+3].c));
        tgt3 = (v / NSLICE) * NSLICE + NSLICE;
    }

    // ---------------- register-preload weight slices, d-contiguous layout ----------------
    // lane l owns cat-dims d = 8l .. 8l+7. Bilinear rows: 24 raw floats (3 per d).
    const int kB  = (s << 3) + w;           // phase B/E/F channel
    const int idx = (s << 4) + (w << 1);    // phase C/D pair base
    const int jCD = idx >> 7;
    const int k0  = idx & 127, k1 = k0 + 1;

    float wBr[24], wC0r[24], wC1r[24], wEr[24];
    float wD0r[8], wD1r[8], wFr[8];
    {
        const float4* pB  = (const float4*)(Wb2 + (long)kB * 768 + 24 * l);
        const float4* pC0 = (const float4*)(Wb1 + (long)k0 * 768 + 24 * l);
        const float4* pC1 = (const float4*)(Wb1 + (long)k1 * 768 + 24 * l);
        const float4* pE  = (const float4*)(Wb0 + (long)kB * 768 + 24 * l);
        #pragma unroll
        for (int i = 0; i < 6; i++) {
            ((float4*)wBr)[i]  = pB[i];
            ((float4*)wC0r)[i] = pC0[i];
            ((float4*)wC1r)[i] = pC1[i];
            ((float4*)wEr)[i]  = pE[i];
        }
        const float4* pD0 = (const float4*)(Ws1 + (long)k0 * 256 + 8 * l);
        const float4* pD1 = (const float4*)(Ws1 + (long)k1 * 256 + 8 * l);
        const float4* pF  = (const float4*)(Ws0 + (long)kB * 256 + 8 * l);
        ((float4*)wD0r)[0] = pD0[0]; ((float4*)wD0r)[1] = pD0[1];
        ((float4*)wD1r)[0] = pD1[0]; ((float4*)wD1r)[1] = pD1[1];
        ((float4*)wFr)[0]  = pF[0];  ((float4*)wFr)[1]  = pF[1];
    }
    const float bB  = bb2[kB];
    const float bC0 = bb1[k0], bC1 = bb1[k1];
    const float bD0 = bs1[k0], bD1 = bs1[k1];
    const float bE  = bb0[kB], bF = bs0[kB];
    const float AL = a_leaf[0], A2 = a2p[0], A1 = a1p[0], A0 = a0p[0];

    __shared__ int sp[12], sn2[5], sl1[2];
    __shared__ __align__(16) float svec2[5][3];
    __shared__ __align__(16) float svec1[2][3];
    __shared__ __align__(16) float svec0[3];
    __shared__ __align__(16) float leaf[12][DIM];  // rows contiguous: [2j]||[2j+1] = 256 cat

    // ---- resolve the (batch-invariant) dependency cone ----
    if (tid == 0) {
        int l1a = cl0[0];
        int l1b = cr0[0];
        sl1[0] = l1a; sl1[1] = l1b;
        int n0 = cl1[l1a], n1 = cr1[l1a], n2_ = cl1[l1b], n3 = cr1[l1b], n4 = cs0[0];
        sn2[0] = n0; sn2[1] = n1; sn2[2] = n2_; sn2[3] = n3; sn2[4] = n4;
        sp[0] = cl2[n0];  sp[1] = cr2[n0];
        sp[2] = cl2[n1];  sp[3] = cr2[n1];
        sp[4] = cl2[n2_]; sp[5] = cr2[n2_];
        sp[6] = cl2[n3];  sp[7] = cr2[n3];
        sp[8] = cl2[n4];  sp[9] = cr2[n4];
        sp[10] = cs1[l1a]; sp[11] = cs1[l1b];
    }
    __syncthreads();

    // ---- preload vec gathers into smem ----
    if (tid < 15) {
        int j = tid / 3, v = tid - 3 * j;
        svec2[j][v] = vec2[((long)b * N2n + sn2[j]) * 3 + v];
    } else if (tid < 21) {
        int t = tid - 15;
        int j = t / 3, v = t - 3 * j;
        svec1[j][v] = vec1[((long)b * N1n + sl1[j]) * 3 + v];
    } else if (tid < 24) {
        svec0[tid - 21] = vec0[(long)b * 3 + (tid - 21)];
    }

    // ---- leaves: 12 rows, h3 = prelu(points @ Wp^T + bp) ----
    for (int i = tid; i < 12 * DIM; i += NTHREADS) {
        int j = i >> 7, k = i & 127;
        const float* pt = points + ((long)b * N3 + sp[j]) * 3;
        float h = fmaf(Wp[k * 3 + 0], pt[0],
                  fmaf(Wp[k * 3 + 1], pt[1],
                  fmaf(Wp[k * 3 + 2], pt[2], bp[k])));
        leaf[j][k] = prelu_f(h, AL);
    }
    __syncthreads();

    // ---- Phase B: layer-2 bilinear, 5 nodes; x from smem, 3-acc per node ----
    {
        #pragma unroll
        for (int j = 0; j < 5; j++) {
            float x[8];
            ld8(&leaf[2 * j][0] + 8 * l, x);       // 256-cat, contiguous rows
            float a0 = 0.f, a1 = 0.f, a2 = 0.f;
            #pragma unroll
            for (int m = 0; m < 8; m++) {
                a0 = fmaf(x[m], wBr[3 * m + 0], a0);
                a1 = fmaf(x[m], wBr[3 * m + 1], a1);
                a2 = fmaf(x[m], wBr[3 * m + 2], a2);
            }
            float z = a0 * svec2[j][0] + a1 * svec2[j][1] + a2 * svec2[j][2];
            float r = wred(z);
            if (l == 0) g_h2[b][j][kB] = prelu_f(r + bB, A2);
        }
    }
    red_bar(b * 4 + 0, tgt0);

    // ---- Phase C: layer-1 bilinear; x straight from global (L2-hot) ----
    {
        float x[8];
        ld8(&g_h2[b][2 * jCD][0] + 8 * l, x);      // rows 2j||2j+1 contiguous
        float a00 = 0.f, a01 = 0.f, a02 = 0.f;
        float a10 = 0.f, a11 = 0.f, a12 = 0.f;
        #pragma unroll
        for (int m = 0; m < 8; m++) {
            a00 = fmaf(x[m], wC0r[3 * m + 0], a00);
            a01 = fmaf(x[m], wC0r[3 * m + 1], a01);
            a02 = fmaf(x[m], wC0r[3 * m + 2], a02);
            a10 = fmaf(x[m], wC1r[3 * m + 0], a10);
            a11 = fmaf(x[m], wC1r[3 * m + 1], a11);
            a12 = fmaf(x[m], wC1r[3 * m + 2], a12);
        }
        float z0 = a00 * svec1[jCD][0] + a01 * svec1[jCD][1] + a02 * svec1[jCD][2];
        float z1 = a10 * svec1[jCD][0] + a11 * svec1[jCD][1] + a12 * svec1[jCD][2];
        float r0 = wred(z0), r1 = wred(z1);
        if (l == 0)      g_tb[b][jCD][k0] = prelu_f(r0 + bC0, A1);
        else if (l == 1) g_tb[b][jCD][k1] = prelu_f(r1 + bC1, A1);
    }
    red_bar(b * 4 + 1, tgt1);

    // ---- Phase D: sample-merge linear; lanes 0-15 read tb (global), 16-31 leaf (smem) ----
    {
        float x[8];
        if (l < 16) ld8(&g_tb[b][jCD][0] + 8 * l, x);
        else        ld8(&leaf[10 + jCD][0] + 8 * (l - 16), x);
        float a0 = 0.f, a1 = 0.f;
        #pragma unroll
        for (int m = 0; m < 8; m++) {
            a0 = fmaf(x[m], wD0r[m], a0);
            a1 = fmaf(x[m], wD1r[m], a1);
        }
        float r0 = wred(a0), r1 = wred(a1);
        if (l == 0)      g_h1[b][jCD][k0] = prelu_f(r0 + bD0, A1);
        else if (l == 1) g_h1[b][jCD][k1] = prelu_f(r1 + bD1, A1);
    }
    red_bar(b * 4 + 2, tgt2);

    // ---- Phase E: root bilinear; x = h1 cat (contiguous global) ----
    {
        float x[8];
        ld8(&g_h1[b][0][0] + 8 * l, x);
        float a0 = 0.f, a1 = 0.f, a2 = 0.f;
        #pragma unroll
        for (int m = 0; m < 8; m++) {
            a0 = fmaf(x[m], wEr[3 * m + 0], a0);
            a1 = fmaf(x[m], wEr[3 * m + 1], a1);
            a2 = fmaf(x[m], wEr[3 * m + 2], a2);
        }
        float z = a0 * svec0[0] + a1 * svec0[1] + a2 * svec0[2];
        float r = wred(z);
        if (l == 0) g_tb0[b][kB] = prelu_f(r + bE, A0);
    }
    red_bar(b * 4 + 3, tgt3);

    // ---- Phase F: root linear; lanes 0-15 read tb0, 16-31 h2[4] (both L2-hot) ----
    {
        float x[8];
        if (l < 16) ld8(&g_tb0[b][0] + 8 * l, x);
        else        ld8(&g_h2[b][4][0] + 8 * (l - 16), x);
        float acc = 0.f;
        #pragma unroll
        for (int m = 0; m < 8; m++) acc = fmaf(x[m], wFr[m], acc);
        float r = wred(acc);
        if (l == 0) out[(long)b * DIM + kB] = prelu_f(r + bF, A0);
    }
}

extern "C" void kernel_launch(void* const* d_in, const int* in_sizes, int n_in,
                              void* d_out, int out_size)
{
    const float* points = (const float*)d_in[0];
    const float* vec2   = (const float*)d_in[1];
    const float* vec1   = (const float*)d_in[2];
    const float* vec0   = (const float*)d_in[3];
    const float* Wp     = (const float*)d_in[4];
    const float* bp     = (const float*)d_in[5];
    const float* a_leaf = (const float*)d_in[6];
    const float* Wb2    = (const float*)d_in[7];
    const float* bb2    = (const float*)d_in[8];
    const float* a2     = (const float*)d_in[9];
    const float* Wb1    = (const float*)d_in[10];
    const float* bb1    = (const float*)d_in[11];
    const float* Ws1    = (const float*)d_in[12];
    const float* bs1    = (const float*)d_in[13];
    const float* a1     = (const float*)d_in[14];
    const float* Wb0    = (const float*)d_in[15];
    const float* bb0    = (const float*)d_in[16];
    const float* Ws0    = (const float*)d_in[17];
    const float* bs0    = (const float*)d_in[18];
    const float* a0     = (const float*)d_in[19];
    const int*   cl2    = (const int*)d_in[20];
    const int*   cr2    = (const int*)d_in[21];
    const int*   cl1    = (const int*)d_in[22];
    const int*   cr1    = (const int*)d_in[23];
    const int*   cs1    = (const int*)d_in[24];
    const int*   cl0    = (const int*)d_in[25];
    const int*   cr0    = (const int*)d_in[26];
    const int*   cs0    = (const int*)d_in[27];

    const int B  = out_size / DIM;          // 8
    const int N3 = in_sizes[0] / (3 * B);   // 131072
    const int N2 = in_sizes[1] / (3 * B);   // 65536
    const int N1 = in_sizes[2] / (3 * B);   // 1024

    encoder_fused_kernel<<<B * NSLICE, NTHREADS>>>(
        points, vec2, vec1, vec0,
        Wp, bp, a_leaf, Wb2, bb2, a2,
        Wb1, bb1, Ws1, bs1, a1,
        Wb0, bb0, Ws0, bs0, a0,
        cl2, cr2, cl1, cr1, cs1, cl0, cr0, cs0,
        (float*)d_out, N3, N2, N1);
}